// round 14
// baseline (speedup 1.0000x reference)
#include <cuda_runtime.h>
#include <cuda_fp16.h>
#include <mma.h>
#include <math.h>
#include <cstdint>

using namespace nvcuda;

#define NTOK 8192
#define SEQ  512
#define DC   1024
#define DP   64
#define NT   8
#define DH   4096

#define BM 128
#define BN 128
#define BK 32
#define STAGES 4
#define MAXSTRIP 72
#define NCTA 304

#define A_ROWPAD_H 40
#define B_ROWPAD_H 136
#define A_STAGE_H (BM * A_ROWPAD_H)
#define B_STAGE_H (BK * B_ROWPAD_H)
#define STAGE_H   (A_STAGE_H + B_STAGE_H)
#define SMEM_DYN  (STAGES * STAGE_H * 2)
#define C_ROWPAD  (BN + 4)

// ------------------------- device scratch (static) -------------------------
__device__ __half g_xh [NTOK * DC];
__device__ __half g_W1h[NT * DC * DH];
__device__ __half g_W2h[NT * DH * DC];
__device__ __half g_H  [(NTOK + NT*BM) * DH];
__device__ int    g_bucket[NT][NTOK];
__device__ int    g_counts[NT];
__device__ int    g_pp[NT];
__device__ int    g_nstrips;
__device__ int    g_strip_tile[MAXSTRIP];
__device__ int    g_strip_row0[MAXSTRIP];
__device__ int    g_strip_done[MAXSTRIP];
__device__ int    g_next;
__device__ int    g_w2_ready;

// ------------------------------- helpers -----------------------------------
__device__ __forceinline__ uint32_t cvta_s(const void* p) {
    uint32_t a;
    asm("{ .reg .u64 t; cvta.to.shared.u64 t, %1; cvt.u32.u64 %0, t; }" : "=r"(a) : "l"(p));
    return a;
}
__device__ __forceinline__ void cp16(uint32_t dst, const void* src) {
    asm volatile("cp.async.cg.shared.global.L2::256B [%0], [%1], 16;" :: "r"(dst), "l"(src));
}
#define CP_COMMIT() asm volatile("cp.async.commit_group;" ::: "memory")
#define CP_WAIT(N)  asm volatile("cp.async.wait_group %0;" :: "n"(N) : "memory")

__device__ __forceinline__ float gelu_exact(float v) {
    return 0.5f * v * (1.0f + erff(v * 0.70710678118654752f));
}

// ------------------------------ small kernels ------------------------------
__global__ void zero_counts_kernel() {
    int i = threadIdx.x;
    if (i < NT) g_counts[i] = 0;
    if (i == NT)     g_next = 0;
    if (i == NT + 1) g_w2_ready = 0;
    if (i >= 16 && i < 16 + MAXSTRIP) g_strip_done[i - 16] = 0;
}
__global__ void w2flag_kernel() {
    __threadfence();
    atomicAdd(&g_w2_ready, 1);
}
__global__ void finalize_kernel() {
    int off = 0, ns = 0;
    for (int t = 0; t < NT; t++) {
        g_pp[t] = off;
        int cnt = g_counts[t];
        int strips = (cnt + BM - 1) / BM;
        for (int s = 0; s < strips; s++) {
            g_strip_tile[ns] = t;
            g_strip_row0[ns] = s * BM;
            ns++;
        }
        off += strips * BM;
    }
    g_nstrips = ns;
}

// fp32 -> fp16 convert: 8192 floats per 256-thread block, MLP=8.
__global__ __launch_bounds__(256) void convert_f2h_kernel(const float* __restrict__ src,
                                                          __half* __restrict__ dst) {
    const size_t base = (size_t)blockIdx.x * 8192;
    const int tid = threadIdx.x;
    float4 v[8];
    #pragma unroll
    for (int i = 0; i < 8; i++)
        v[i] = *(const float4*)(src + base + (size_t)(i*256 + tid) * 4);
    #pragma unroll
    for (int i = 0; i < 8; i++) {
        __half2 h0 = __floats2half2_rn(v[i].x, v[i].y);
        __half2 h1 = __floats2half2_rn(v[i].z, v[i].w);
        *(uint2*)(dst + base + (size_t)(i*256 + tid) * 4) =
            make_uint2(*(uint32_t*)&h0, *(uint32_t*)&h1);
    }
}

// ------------------- routing (+ fused x -> fp16 convert) -------------------
__global__ void routing_kernel(const float* __restrict__ x,
                               const float* __restrict__ pe,
                               const float* __restrict__ pwp,
                               const float* __restrict__ cwp,
                               const float* __restrict__ pos_sigs,
                               const float* __restrict__ content_sigs)
{
    __shared__ float s_csig[NT][DC];
    __shared__ float s_psig[NT][DP];
    int tid = threadIdx.x;
    for (int i = tid; i < NT*DC; i += blockDim.x) {
        float v = content_sigs[i];
        ((float*)s_csig)[i] = (v > 0.f) ? 1.f : ((v < 0.f) ? -1.f : 0.f);
    }
    for (int i = tid; i < NT*DP; i += blockDim.x) {
        float v = pos_sigs[i];
        ((float*)s_psig)[i] = (v > 0.f) ? 1.f : ((v < 0.f) ? -1.f : 0.f);
    }
    __syncthreads();

    float pw = 1.f / (1.f + expf(-pwp[0]));
    float cw = 1.f / (1.f + expf(-cwp[0]));
    float tot = pw + cw;
    pw /= tot; cw /= tot;

    int token = (blockIdx.x * blockDim.x + tid) >> 5;
    int lane  = tid & 31;
    if (token >= NTOK) return;
    int s = token % SEQ;

    float acc[NT];
    #pragma unroll
    for (int t = 0; t < NT; t++) acc[t] = 0.f;

    const float4* xr4 = (const float4*)(x + (size_t)token * DC);
    uint2* xh4 = (uint2*)(g_xh + (size_t)token * DC);
    #pragma unroll 2
    for (int j4 = lane; j4 < DC/4; j4 += 32) {
        float4 xv = xr4[j4];
        __half2 h0 = __floats2half2_rn(xv.x, xv.y);
        __half2 h1 = __floats2half2_rn(xv.z, xv.w);
        xh4[j4] = make_uint2(*(uint32_t*)&h0, *(uint32_t*)&h1);
        #pragma unroll
        for (int t = 0; t < NT; t++) {
            float4 sv = *(const float4*)&s_csig[t][j4*4];
            acc[t] += xv.x*sv.x + xv.y*sv.y + xv.z*sv.z + xv.w*sv.w;
        }
    }
    #pragma unroll
    for (int t = 0; t < NT; t++) acc[t] *= cw;

    for (int j = lane; j < DP; j += 32) {
        float pv = pe[s*DP + j] * pw;
        #pragma unroll
        for (int t = 0; t < NT; t++) acc[t] += pv * s_psig[t][j];
    }
    #pragma unroll
    for (int t = 0; t < NT; t++) {
        #pragma unroll
        for (int o = 16; o > 0; o >>= 1)
            acc[t] += __shfl_xor_sync(0xffffffffu, acc[t], o);
    }
    if (lane == 0) {
        int best = 0; float bv = acc[0];
        #pragma unroll
        for (int t = 1; t < NT; t++)
            if (acc[t] > bv) { bv = acc[t]; best = t; }
        int pos = atomicAdd(&g_counts[best], 1);
        g_bucket[best][pos] = token;
    }
}

// ===========================================================================
// Fused persistent MoE kernel: dynamic work queue over gemm1 tiles (items
// [0, ns*32)) then gemm2 tiles (items [ns*32, ns*40)). Per-strip dependency
// counters release gemm2 tiles as soon as their strip's H rows are complete.
// Round-8 proven mainloop in both paths.
// ===========================================================================
__global__ __launch_bounds__(128, 2) void moe_kernel(const float* __restrict__ b1,
                                                     const float* __restrict__ b2,
                                                     float* __restrict__ out)
{
    extern __shared__ __half smem[];
    __shared__ float s_bias[BN];
    __shared__ int   s_rows[BM];
    __shared__ int   s_item[1];

    const int tid = threadIdx.x;
    const int wid = tid >> 5;
    const int wm  = wid >> 1, wn = wid & 1;
    const uint32_t smem_u = cvta_s(smem);

    const int ns   = g_nstrips;
    const int n1   = ns * 32;
    const int ntot = n1 + ns * 8;

    for (;;) {
        if (tid == 0) s_item[0] = atomicAdd(&g_next, 1);
        __syncthreads();
        const int item = s_item[0];
        if (item >= ntot) break;

        if (item < n1) {
            // ---------------- GEMM1 tile: H = gelu(x @ W1 + b1) ----------------
            const int sid  = item >> 5;
            const int n0   = (item & 31) << 7;
            const int t    = g_strip_tile[sid];
            const int row0 = g_strip_row0[sid];
            const int cnt  = g_counts[t];

            s_bias[tid] = b1[(size_t)t * DH + n0 + tid];

            const int ar = tid >> 2;
            const int ac = tid & 3;
            const __half* aptr[4];
            #pragma unroll
            for (int i = 0; i < 4; i++) {
                int idx = row0 + ar + i * 32;
                if (idx > cnt - 1) idx = cnt - 1;
                aptr[i] = g_xh + (size_t)g_bucket[t][idx] * DC + ac * 8;
            }
            const int br = tid >> 4;
            const int bc = tid & 15;
            const __half* Wt = g_W1h + (size_t)t * DC * DH + n0 + bc * 8;

            auto fill = [&](int j) {
                const int s = j % STAGES;
                const int k0 = j * BK;
                uint32_t aBase = smem_u + (uint32_t)(s * STAGE_H) * 2u;
                uint32_t bBase = aBase + A_STAGE_H * 2u;
                #pragma unroll
                for (int i = 0; i < 4; i++)
                    cp16(aBase + (uint32_t)(ar + i*32) * (A_ROWPAD_H*2u) + (uint32_t)ac * 16u,
                         aptr[i] + k0);
                #pragma unroll
                for (int i = 0; i < 4; i++)
                    cp16(bBase + (uint32_t)(br + i*8) * (B_ROWPAD_H*2u) + (uint32_t)bc * 16u,
                         Wt + (size_t)(k0 + br + i*8) * DH);
                CP_COMMIT();
            };

            wmma::fragment<wmma::accumulator, 16, 16, 16, float> cf[4][4];
            #pragma unroll
            for (int i = 0; i < 4; i++)
                #pragma unroll
                for (int j = 0; j < 4; j++)
                    wmma::fill_fragment(cf[i][j], 0.f);

            const int NITER = DC / BK;   // 32
            fill(0); fill(1); fill(2);

            for (int i = 0; i < NITER; i++) {
                if      (i + 3 <= NITER) { CP_WAIT(2); }
                else if (i + 2 == NITER) { CP_WAIT(1); }
                else                     { CP_WAIT(0); }
                __syncthreads();
                if (i + 3 < NITER) fill(i + 3);

                const __half* sA = smem + (i % STAGES) * STAGE_H;
                const __half* sB = sA + A_STAGE_H;

                #pragma unroll
                for (int kk = 0; kk < BK; kk += 16) {
                    wmma::fragment<wmma::matrix_a, 16, 16, 16, __half, wmma::row_major> af[4];
                    wmma::fragment<wmma::matrix_b, 16, 16, 16, __half, wmma::row_major> bf[4];
                    #pragma unroll
                    for (int m = 0; m < 4; m++)
                        wmma::load_matrix_sync(af[m], sA + (wm*64 + m*16) * A_ROWPAD_H + kk, A_ROWPAD_H);
                    #pragma unroll
                    for (int n = 0; n < 4; n++)
                        wmma::load_matrix_sync(bf[n], sB + kk * B_ROWPAD_H + wn*64 + n*16, B_ROWPAD_H);
                    #pragma unroll
                    for (int m = 0; m < 4; m++)
                        #pragma unroll
                        for (int n = 0; n < 4; n++)
                            wmma::mma_sync(cf[m][n], af[m], bf[n], cf[m][n]);
                }
            }

            __syncthreads();
            float* sC = (float*)smem;
            #pragma unroll
            for (int m = 0; m < 4; m++)
                #pragma unroll
                for (int n = 0; n < 4; n++)
                    wmma::store_matrix_sync(sC + (wm*64 + m*16) * C_ROWPAD + wn*64 + n*16,
                                            cf[m][n], C_ROWPAD, wmma::mem_row_major);
            __syncthreads();

            __half* Hbase = g_H + (size_t)(g_pp[t] + row0) * DH + n0;
            #pragma unroll
            for (int i = 0; i < 32; i++) {
                int idx = tid + i * 128;
                int r = idx >> 5, c4 = idx & 31;
                float4 v = *(float4*)(sC + r * C_ROWPAD + c4 * 4);
                v.x = gelu_exact(v.x + s_bias[c4*4 + 0]);
                v.y = gelu_exact(v.y + s_bias[c4*4 + 1]);
                v.z = gelu_exact(v.z + s_bias[c4*4 + 2]);
                v.w = gelu_exact(v.w + s_bias[c4*4 + 3]);
                __half2 h0 = __floats2half2_rn(v.x, v.y);
                __half2 h1 = __floats2half2_rn(v.z, v.w);
                *(uint2*)(Hbase + (size_t)r * DH + c4 * 4) =
                    make_uint2(*(uint32_t*)&h0, *(uint32_t*)&h1);
            }

            __threadfence();                   // release H stores
            __syncthreads();
            if (tid == 0) atomicAdd(&g_strip_done[sid], 1);
        } else {
            // ---------------- GEMM2 tile: out = H @ W2 + b2 (scatter) ----------
            const int j    = item - n1;
            const int sid  = j >> 3;
            const int n0   = (j & 7) << 7;
            const int t    = g_strip_tile[sid];
            const int row0 = g_strip_row0[sid];
            const int cnt  = g_counts[t];

            if (tid == 0) {
                while (atomicAdd(&g_w2_ready, 0) < 2) { }         // W2h converted
                while (atomicAdd(&g_strip_done[sid], 0) < 32) { } // H strip ready
                __threadfence();                                  // acquire
            }
            __syncthreads();

            s_bias[tid] = b2[(size_t)t * DC + n0 + tid];
            {
                int r = row0 + tid;
                s_rows[tid] = (r < cnt) ? g_bucket[t][r] : -1;
            }

            const int ar = tid >> 2;
            const int ac = tid & 3;
            const size_t hrow0 = (size_t)(g_pp[t] + row0);
            const __half* aptr[4];
            #pragma unroll
            for (int i = 0; i < 4; i++)
                aptr[i] = g_H + (hrow0 + ar + i * 32) * DH + ac * 8;

            const int br = tid >> 4;
            const int bc = tid & 15;
            const __half* Wt = g_W2h + (size_t)t * DH * DC + n0 + bc * 8;

            auto fill = [&](int jj) {
                const int s = jj % STAGES;
                const int k0 = jj * BK;
                uint32_t aBase = smem_u + (uint32_t)(s * STAGE_H) * 2u;
                uint32_t bBase = aBase + A_STAGE_H * 2u;
                #pragma unroll
                for (int i = 0; i < 4; i++)
                    cp16(aBase + (uint32_t)(ar + i*32) * (A_ROWPAD_H*2u) + (uint32_t)ac * 16u,
                         aptr[i] + k0);
                #pragma unroll
                for (int i = 0; i < 4; i++)
                    cp16(bBase + (uint32_t)(br + i*8) * (B_ROWPAD_H*2u) + (uint32_t)bc * 16u,
                         Wt + (size_t)(k0 + br + i*8) * DC);
                CP_COMMIT();
            };

            wmma::fragment<wmma::accumulator, 16, 16, 16, float> cf[4][4];
            #pragma unroll
            for (int i = 0; i < 4; i++)
                #pragma unroll
                for (int jj = 0; jj < 4; jj++)
                    wmma::fill_fragment(cf[i][jj], 0.f);

            const int NITER = DH / BK;   // 128
            fill(0); fill(1); fill(2);

            for (int i = 0; i < NITER; i++) {
                if      (i + 3 <= NITER) { CP_WAIT(2); }
                else if (i + 2 == NITER) { CP_WAIT(1); }
                else                     { CP_WAIT(0); }
                __syncthreads();
                if (i + 3 < NITER) fill(i + 3);

                const __half* sA = smem + (i % STAGES) * STAGE_H;
                const __half* sB = sA + A_STAGE_H;

                #pragma unroll
                for (int kk = 0; kk < BK; kk += 16) {
                    wmma::fragment<wmma::matrix_a, 16, 16, 16, __half, wmma::row_major> af[4];
                    wmma::fragment<wmma::matrix_b, 16, 16, 16, __half, wmma::row_major> bf[4];
                    #pragma unroll
                    for (int m = 0; m < 4; m++)
                        wmma::load_matrix_sync(af[m], sA + (wm*64 + m*16) * A_ROWPAD_H + kk, A_ROWPAD_H);
                    #pragma unroll
                    for (int n = 0; n < 4; n++)
                        wmma::load_matrix_sync(bf[n], sB + kk * B_ROWPAD_H + wn*64 + n*16, B_ROWPAD_H);
                    #pragma unroll
                    for (int m = 0; m < 4; m++)
                        #pragma unroll
                        for (int n = 0; n < 4; n++)
                            wmma::mma_sync(cf[m][n], af[m], bf[n], cf[m][n]);
                }
            }

            __syncthreads();
            float* sC = (float*)smem;
            #pragma unroll
            for (int m = 0; m < 4; m++)
                #pragma unroll
                for (int n = 0; n < 4; n++)
                    wmma::store_matrix_sync(sC + (wm*64 + m*16) * C_ROWPAD + wn*64 + n*16,
                                            cf[m][n], C_ROWPAD, wmma::mem_row_major);
            __syncthreads();

            #pragma unroll
            for (int i = 0; i < 32; i++) {
                int idx = tid + i * 128;
                int r = idx >> 5, c4 = idx & 31;
                int tok = s_rows[r];
                if (tok >= 0) {
                    float4 v = *(float4*)(sC + r * C_ROWPAD + c4 * 4);
                    v.x += s_bias[c4*4 + 0];
                    v.y += s_bias[c4*4 + 1];
                    v.z += s_bias[c4*4 + 2];
                    v.w += s_bias[c4*4 + 3];
                    *(float4*)(out + (size_t)tok * DC + n0 + c4 * 4) = v;
                }
            }
        }
        __syncthreads();   // protect smem reuse before next item
    }
}

// ------------------------------- launcher ----------------------------------
extern "C" void kernel_launch(void* const* d_in, const int* in_sizes, int n_in,
                              void* d_out, int out_size)
{
    const float* x            = (const float*)d_in[0];
    const float* pe           = (const float*)d_in[1];
    const float* pwp          = (const float*)d_in[2];
    const float* cwp          = (const float*)d_in[3];
    const float* pos_sigs     = (const float*)d_in[4];
    const float* content_sigs = (const float*)d_in[5];
    const float* W1           = (const float*)d_in[6];
    const float* b1           = (const float*)d_in[7];
    const float* W2           = (const float*)d_in[8];
    const float* b2           = (const float*)d_in[9];
    float* out = (float*)d_out;

    static cudaStream_t s1 = nullptr, s2 = nullptr;
    static cudaEvent_t  ev0 = nullptr, ev1a = nullptr, ev1b = nullptr,
                        ev2a = nullptr, ev2b = nullptr;
    static int ready = 0;
    if (!ready) {
        cudaFuncSetAttribute(moe_kernel, cudaFuncAttributeMaxDynamicSharedMemorySize, SMEM_DYN);
        cudaStreamCreateWithFlags(&s1, cudaStreamNonBlocking);
        cudaStreamCreateWithFlags(&s2, cudaStreamNonBlocking);
        cudaEventCreateWithFlags(&ev0,  cudaEventDisableTiming);
        cudaEventCreateWithFlags(&ev1a, cudaEventDisableTiming);
        cudaEventCreateWithFlags(&ev1b, cudaEventDisableTiming);
        cudaEventCreateWithFlags(&ev2a, cudaEventDisableTiming);
        cudaEventCreateWithFlags(&ev2b, cudaEventDisableTiming);
        ready = 1;
    }

    __half* w1h; cudaGetSymbolAddress((void**)&w1h, g_W1h);
    __half* w2h; cudaGetSymbolAddress((void**)&w2h, g_W2h);

    const int WBLK  = NT*DC*DH/8192;
    const int HALF  = WBLK/2;
    const size_t HOFF = (size_t)HALF * 8192;

    // zero state FIRST (w2 flag / queue / counters), then fork converts.
    zero_counts_kernel<<<1, 128>>>();
    cudaEventRecord(ev0, 0);
    cudaStreamWaitEvent(s1, ev0, 0);
    cudaStreamWaitEvent(s2, ev0, 0);

    convert_f2h_kernel<<<HALF, 256, 0, s1>>>(W1,        w1h);
    cudaEventRecord(ev1a, s1);
    convert_f2h_kernel<<<HALF, 256, 0, s2>>>(W1 + HOFF, w1h + HOFF);
    cudaEventRecord(ev1b, s2);

    convert_f2h_kernel<<<HALF, 256, 0, s1>>>(W2,        w2h);
    w2flag_kernel<<<1, 1, 0, s1>>>();
    cudaEventRecord(ev2a, s1);
    convert_f2h_kernel<<<HALF, 256, 0, s2>>>(W2 + HOFF, w2h + HOFF);
    w2flag_kernel<<<1, 1, 0, s2>>>();
    cudaEventRecord(ev2b, s2);

    routing_kernel<<<NTOK/8, 256>>>(x, pe, pwp, cwp, pos_sigs, content_sigs);
    finalize_kernel<<<1, 1>>>();

    // moe needs only W1h + routing before it starts (W2 gated in-kernel).
    cudaStreamWaitEvent(0, ev1a, 0);
    cudaStreamWaitEvent(0, ev1b, 0);
    moe_kernel<<<NCTA, 128, SMEM_DYN>>>(b1, b2, out);

    // Join the remaining side-stream work into the capture-origin stream
    // AFTER the moe launch: closes the graph fork without serializing moe
    // behind the W2 converts.
    cudaStreamWaitEvent(0, ev2a, 0);
    cudaStreamWaitEvent(0, ev2b, 0);
}

// round 16
// speedup vs baseline: 1.1271x; 1.1271x over previous
#include <cuda_runtime.h>
#include <cuda_fp16.h>
#include <mma.h>
#include <math.h>
#include <cstdint>

using namespace nvcuda;

#define NTOK 8192
#define SEQ  512
#define DC   1024
#define DP   64
#define NT   8
#define DH   4096

#define BM 128
#define BN 128
#define BK 32
#define STAGES 4
#define MAXG 68                       // strips per group (4 tiles, worst-case skew)

#define A_ROWPAD_H 40
#define B_ROWPAD_H 136
#define A_STAGE_H (BM * A_ROWPAD_H)
#define B_STAGE_H (BK * B_ROWPAD_H)
#define STAGE_H   (A_STAGE_H + B_STAGE_H)
#define SMEM_DYN  (STAGES * STAGE_H * 2)
#define C_ROWPAD  (BN + 4)

// ------------------------- device scratch (static) -------------------------
__device__ __half g_xh [NTOK * DC];
__device__ __half g_W1h[NT * DC * DH];
__device__ __half g_W2h[NT * DH * DC];
__device__ __half g_H  [(NTOK + NT*BM) * DH];
__device__ int    g_bucket[NT][NTOK];
__device__ int    g_counts[NT];
__device__ int    g_pp[NT];
__device__ int    g_ns[2];
__device__ int    g_stile[2][MAXG];
__device__ int    g_srow [2][MAXG];

// ------------------------------- helpers -----------------------------------
__device__ __forceinline__ uint32_t cvta_s(const void* p) {
    uint32_t a;
    asm("{ .reg .u64 t; cvta.to.shared.u64 t, %1; cvt.u32.u64 %0, t; }" : "=r"(a) : "l"(p));
    return a;
}
__device__ __forceinline__ void cp16(uint32_t dst, const void* src) {
    asm volatile("cp.async.cg.shared.global.L2::256B [%0], [%1], 16;" :: "r"(dst), "l"(src));
}
#define CP_COMMIT() asm volatile("cp.async.commit_group;" ::: "memory")
#define CP_WAIT(N)  asm volatile("cp.async.wait_group %0;" :: "n"(N) : "memory")

__device__ __forceinline__ float gelu_exact(float v) {
    return 0.5f * v * (1.0f + erff(v * 0.70710678118654752f));
}

// ------------------------------ small kernels ------------------------------
__global__ void zero_counts_kernel() {
    if (threadIdx.x < NT) g_counts[threadIdx.x] = 0;
}
__global__ void finalize_kernel() {
    int off = 0;
    for (int t = 0; t < NT; t++) {
        g_pp[t] = off;
        off += ((g_counts[t] + BM - 1) / BM) * BM;
    }
    for (int g = 0; g < 2; g++) {
        int ns = 0;
        for (int t = g*4; t < g*4 + 4; t++) {
            int strips = (g_counts[t] + BM - 1) / BM;
            for (int s = 0; s < strips && ns < MAXG; s++) {
                g_stile[g][ns] = t;
                g_srow [g][ns] = s * BM;
                ns++;
            }
        }
        g_ns[g] = ns;
    }
}

// fp32 -> fp16 convert: 8192 floats per 256-thread block, MLP=8.
__global__ __launch_bounds__(256) void convert_f2h_kernel(const float* __restrict__ src,
                                                          __half* __restrict__ dst) {
    const size_t base = (size_t)blockIdx.x * 8192;
    const int tid = threadIdx.x;
    float4 v[8];
    #pragma unroll
    for (int i = 0; i < 8; i++)
        v[i] = *(const float4*)(src + base + (size_t)(i*256 + tid) * 4);
    #pragma unroll
    for (int i = 0; i < 8; i++) {
        __half2 h0 = __floats2half2_rn(v[i].x, v[i].y);
        __half2 h1 = __floats2half2_rn(v[i].z, v[i].w);
        *(uint2*)(dst + base + (size_t)(i*256 + tid) * 4) =
            make_uint2(*(uint32_t*)&h0, *(uint32_t*)&h1);
    }
}

// ------------------- routing (+ fused x -> fp16 convert) -------------------
__global__ void routing_kernel(const float* __restrict__ x,
                               const float* __restrict__ pe,
                               const float* __restrict__ pwp,
                               const float* __restrict__ cwp,
                               const float* __restrict__ pos_sigs,
                               const float* __restrict__ content_sigs)
{
    __shared__ float s_csig[NT][DC];
    __shared__ float s_psig[NT][DP];
    int tid = threadIdx.x;
    for (int i = tid; i < NT*DC; i += blockDim.x) {
        float v = content_sigs[i];
        ((float*)s_csig)[i] = (v > 0.f) ? 1.f : ((v < 0.f) ? -1.f : 0.f);
    }
    for (int i = tid; i < NT*DP; i += blockDim.x) {
        float v = pos_sigs[i];
        ((float*)s_psig)[i] = (v > 0.f) ? 1.f : ((v < 0.f) ? -1.f : 0.f);
    }
    __syncthreads();

    float pw = 1.f / (1.f + expf(-pwp[0]));
    float cw = 1.f / (1.f + expf(-cwp[0]));
    float tot = pw + cw;
    pw /= tot; cw /= tot;

    int token = (blockIdx.x * blockDim.x + tid) >> 5;
    int lane  = tid & 31;
    if (token >= NTOK) return;
    int s = token % SEQ;

    float acc[NT];
    #pragma unroll
    for (int t = 0; t < NT; t++) acc[t] = 0.f;

    const float4* xr4 = (const float4*)(x + (size_t)token * DC);
    uint2* xh4 = (uint2*)(g_xh + (size_t)token * DC);
    #pragma unroll 2
    for (int j4 = lane; j4 < DC/4; j4 += 32) {
        float4 xv = xr4[j4];
        __half2 h0 = __floats2half2_rn(xv.x, xv.y);
        __half2 h1 = __floats2half2_rn(xv.z, xv.w);
        xh4[j4] = make_uint2(*(uint32_t*)&h0, *(uint32_t*)&h1);
        #pragma unroll
        for (int t = 0; t < NT; t++) {
            float4 sv = *(const float4*)&s_csig[t][j4*4];
            acc[t] += xv.x*sv.x + xv.y*sv.y + xv.z*sv.z + xv.w*sv.w;
        }
    }
    #pragma unroll
    for (int t = 0; t < NT; t++) acc[t] *= cw;

    for (int j = lane; j < DP; j += 32) {
        float pv = pe[s*DP + j] * pw;
        #pragma unroll
        for (int t = 0; t < NT; t++) acc[t] += pv * s_psig[t][j];
    }
    #pragma unroll
    for (int t = 0; t < NT; t++) {
        #pragma unroll
        for (int o = 16; o > 0; o >>= 1)
            acc[t] += __shfl_xor_sync(0xffffffffu, acc[t], o);
    }
    if (lane == 0) {
        int best = 0; float bv = acc[0];
        #pragma unroll
        for (int t = 1; t < NT; t++)
            if (acc[t] > bv) { bv = acc[t]; best = t; }
        int pos = atomicAdd(&g_counts[best], 1);
        g_bucket[best][pos] = token;
    }
}

// ===========================================================================
// fp16 HMMA GEMMs (round-8/12 proven core), group-compacted grids.
// ===========================================================================

__global__ __launch_bounds__(128, 2) void gemm1_kernel(int grp, const float* __restrict__ b1)
{
    const int sid = blockIdx.x;
    if (sid >= g_ns[grp]) return;
    const int t    = g_stile[grp][sid];
    const int row0 = g_srow [grp][sid];
    const int cnt  = g_counts[t];
    const int n0   = blockIdx.y * BN;

    extern __shared__ __half smem[];
    __shared__ float s_bias[BN];

    const int tid = threadIdx.x;
    const int wid = tid >> 5;
    const int wm  = wid >> 1, wn = wid & 1;

    s_bias[tid] = b1[(size_t)t * DH + n0 + tid];

    const int ar = tid >> 2;
    const int ac = tid & 3;
    const __half* aptr[4];
    #pragma unroll
    for (int i = 0; i < 4; i++) {
        int idx = row0 + ar + i * 32;
        if (idx > cnt - 1) idx = cnt - 1;
        aptr[i] = g_xh + (size_t)g_bucket[t][idx] * DC + ac * 8;
    }
    const int br = tid >> 4;
    const int bc = tid & 15;
    const __half* Wt = g_W1h + (size_t)t * DC * DH + n0 + bc * 8;

    const uint32_t smem_u = cvta_s(smem);
    auto fill = [&](int j) {
        const int s = j % STAGES;
        const int k0 = j * BK;
        uint32_t aBase = smem_u + (uint32_t)(s * STAGE_H) * 2u;
        uint32_t bBase = aBase + A_STAGE_H * 2u;
        #pragma unroll
        for (int i = 0; i < 4; i++)
            cp16(aBase + (uint32_t)(ar + i*32) * (A_ROWPAD_H*2u) + (uint32_t)ac * 16u,
                 aptr[i] + k0);
        #pragma unroll
        for (int i = 0; i < 4; i++)
            cp16(bBase + (uint32_t)(br + i*8) * (B_ROWPAD_H*2u) + (uint32_t)bc * 16u,
                 Wt + (size_t)(k0 + br + i*8) * DH);
        CP_COMMIT();
    };

    wmma::fragment<wmma::accumulator, 16, 16, 16, float> cf[4][4];
    #pragma unroll
    for (int i = 0; i < 4; i++)
        #pragma unroll
        for (int j = 0; j < 4; j++)
            wmma::fill_fragment(cf[i][j], 0.f);

    const int NITER = DC / BK;   // 32
    fill(0); fill(1); fill(2);

    for (int i = 0; i < NITER; i++) {
        if      (i + 3 <= NITER) { CP_WAIT(2); }
        else if (i + 2 == NITER) { CP_WAIT(1); }
        else                     { CP_WAIT(0); }
        __syncthreads();
        if (i + 3 < NITER) fill(i + 3);

        const __half* sA = smem + (i % STAGES) * STAGE_H;
        const __half* sB = sA + A_STAGE_H;

        #pragma unroll
        for (int kk = 0; kk < BK; kk += 16) {
            wmma::fragment<wmma::matrix_a, 16, 16, 16, __half, wmma::row_major> af[4];
            wmma::fragment<wmma::matrix_b, 16, 16, 16, __half, wmma::row_major> bf[4];
            #pragma unroll
            for (int m = 0; m < 4; m++)
                wmma::load_matrix_sync(af[m], sA + (wm*64 + m*16) * A_ROWPAD_H + kk, A_ROWPAD_H);
            #pragma unroll
            for (int n = 0; n < 4; n++)
                wmma::load_matrix_sync(bf[n], sB + kk * B_ROWPAD_H + wn*64 + n*16, B_ROWPAD_H);
            #pragma unroll
            for (int m = 0; m < 4; m++)
                #pragma unroll
                for (int n = 0; n < 4; n++)
                    wmma::mma_sync(cf[m][n], af[m], bf[n], cf[m][n]);
        }
    }

    __syncthreads();
    float* sC = (float*)smem;
    #pragma unroll
    for (int m = 0; m < 4; m++)
        #pragma unroll
        for (int n = 0; n < 4; n++)
            wmma::store_matrix_sync(sC + (wm*64 + m*16) * C_ROWPAD + wn*64 + n*16,
                                    cf[m][n], C_ROWPAD, wmma::mem_row_major);
    __syncthreads();

    __half* Hbase = g_H + (size_t)(g_pp[t] + row0) * DH + n0;
    #pragma unroll
    for (int i = 0; i < 32; i++) {
        int idx = tid + i * 128;
        int r = idx >> 5, c4 = idx & 31;
        float4 v = *(float4*)(sC + r * C_ROWPAD + c4 * 4);
        v.x = gelu_exact(v.x + s_bias[c4*4 + 0]);
        v.y = gelu_exact(v.y + s_bias[c4*4 + 1]);
        v.z = gelu_exact(v.z + s_bias[c4*4 + 2]);
        v.w = gelu_exact(v.w + s_bias[c4*4 + 3]);
        __half2 h0 = __floats2half2_rn(v.x, v.y);
        __half2 h1 = __floats2half2_rn(v.z, v.w);
        *(uint2*)(Hbase + (size_t)r * DH + c4 * 4) = make_uint2(*(uint32_t*)&h0, *(uint32_t*)&h1);
    }
}

__global__ __launch_bounds__(128, 2) void gemm2_kernel(int grp, const float* __restrict__ b2,
                                                       float* __restrict__ out)
{
    const int sid = blockIdx.x;
    if (sid >= g_ns[grp]) return;
    const int t    = g_stile[grp][sid];
    const int row0 = g_srow [grp][sid];
    const int cnt  = g_counts[t];
    const int n0   = blockIdx.y * BN;

    extern __shared__ __half smem[];
    __shared__ float s_bias[BN];
    __shared__ int   s_rows[BM];

    const int tid = threadIdx.x;
    const int wid = tid >> 5;
    const int wm  = wid >> 1, wn = wid & 1;

    s_bias[tid] = b2[(size_t)t * DC + n0 + tid];
    {
        int r = row0 + tid;
        s_rows[tid] = (r < cnt) ? g_bucket[t][r] : -1;
    }

    const int ar = tid >> 2;
    const int ac = tid & 3;
    const size_t hrow0 = (size_t)(g_pp[t] + row0);
    const __half* aptr[4];
    #pragma unroll
    for (int i = 0; i < 4; i++)
        aptr[i] = g_H + (hrow0 + ar + i * 32) * DH + ac * 8;

    const int br = tid >> 4;
    const int bc = tid & 15;
    const __half* Wt = g_W2h + (size_t)t * DH * DC + n0 + bc * 8;

    const uint32_t smem_u = cvta_s(smem);
    auto fill = [&](int j) {
        const int s = j % STAGES;
        const int k0 = j * BK;
        uint32_t aBase = smem_u + (uint32_t)(s * STAGE_H) * 2u;
        uint32_t bBase = aBase + A_STAGE_H * 2u;
        #pragma unroll
        for (int i = 0; i < 4; i++)
            cp16(aBase + (uint32_t)(ar + i*32) * (A_ROWPAD_H*2u) + (uint32_t)ac * 16u,
                 aptr[i] + k0);
        #pragma unroll
        for (int i = 0; i < 4; i++)
            cp16(bBase + (uint32_t)(br + i*8) * (B_ROWPAD_H*2u) + (uint32_t)bc * 16u,
                 Wt + (size_t)(k0 + br + i*8) * DC);
        CP_COMMIT();
    };

    wmma::fragment<wmma::accumulator, 16, 16, 16, float> cf[4][4];
    #pragma unroll
    for (int i = 0; i < 4; i++)
        #pragma unroll
        for (int j = 0; j < 4; j++)
            wmma::fill_fragment(cf[i][j], 0.f);

    const int NITER = DH / BK;   // 128
    fill(0); fill(1); fill(2);

    for (int i = 0; i < NITER; i++) {
        if      (i + 3 <= NITER) { CP_WAIT(2); }
        else if (i + 2 == NITER) { CP_WAIT(1); }
        else                     { CP_WAIT(0); }
        __syncthreads();
        if (i + 3 < NITER) fill(i + 3);

        const __half* sA = smem + (i % STAGES) * STAGE_H;
        const __half* sB = sA + A_STAGE_H;

        #pragma unroll
        for (int kk = 0; kk < BK; kk += 16) {
            wmma::fragment<wmma::matrix_a, 16, 16, 16, __half, wmma::row_major> af[4];
            wmma::fragment<wmma::matrix_b, 16, 16, 16, __half, wmma::row_major> bf[4];
            #pragma unroll
            for (int m = 0; m < 4; m++)
                wmma::load_matrix_sync(af[m], sA + (wm*64 + m*16) * A_ROWPAD_H + kk, A_ROWPAD_H);
            #pragma unroll
            for (int n = 0; n < 4; n++)
                wmma::load_matrix_sync(bf[n], sB + kk * B_ROWPAD_H + wn*64 + n*16, B_ROWPAD_H);
            #pragma unroll
            for (int m = 0; m < 4; m++)
                #pragma unroll
                for (int n = 0; n < 4; n++)
                    wmma::mma_sync(cf[m][n], af[m], bf[n], cf[m][n]);
        }
    }

    __syncthreads();
    float* sC = (float*)smem;
    #pragma unroll
    for (int m = 0; m < 4; m++)
        #pragma unroll
        for (int n = 0; n < 4; n++)
            wmma::store_matrix_sync(sC + (wm*64 + m*16) * C_ROWPAD + wn*64 + n*16,
                                    cf[m][n], C_ROWPAD, wmma::mem_row_major);
    __syncthreads();

    #pragma unroll
    for (int i = 0; i < 32; i++) {
        int idx = tid + i * 128;
        int r = idx >> 5, c4 = idx & 31;
        int tok = s_rows[r];
        if (tok >= 0) {
            float4 v = *(float4*)(sC + r * C_ROWPAD + c4 * 4);
            v.x += s_bias[c4*4 + 0];
            v.y += s_bias[c4*4 + 1];
            v.z += s_bias[c4*4 + 2];
            v.w += s_bias[c4*4 + 3];
            *(float4*)(out + (size_t)tok * DC + n0 + c4 * 4) = v;
        }
    }
}

// ------------------------------- launcher ----------------------------------
extern "C" void kernel_launch(void* const* d_in, const int* in_sizes, int n_in,
                              void* d_out, int out_size)
{
    const float* x            = (const float*)d_in[0];
    const float* pe           = (const float*)d_in[1];
    const float* pwp          = (const float*)d_in[2];
    const float* cwp          = (const float*)d_in[3];
    const float* pos_sigs     = (const float*)d_in[4];
    const float* content_sigs = (const float*)d_in[5];
    const float* W1           = (const float*)d_in[6];
    const float* b1           = (const float*)d_in[7];
    const float* W2           = (const float*)d_in[8];
    const float* b2           = (const float*)d_in[9];
    float* out = (float*)d_out;

    static cudaStream_t s1 = nullptr, s2 = nullptr;
    static cudaEvent_t  ev0 = nullptr, ev1a = nullptr, ev1b = nullptr,
                        evR = nullptr, ev2 = nullptr, evT1 = nullptr, evT2 = nullptr;
    static int ready = 0;
    if (!ready) {
        cudaFuncSetAttribute(gemm1_kernel, cudaFuncAttributeMaxDynamicSharedMemorySize, SMEM_DYN);
        cudaFuncSetAttribute(gemm2_kernel, cudaFuncAttributeMaxDynamicSharedMemorySize, SMEM_DYN);
        cudaStreamCreateWithFlags(&s1, cudaStreamNonBlocking);
        cudaStreamCreateWithFlags(&s2, cudaStreamNonBlocking);
        cudaEventCreateWithFlags(&ev0,  cudaEventDisableTiming);
        cudaEventCreateWithFlags(&ev1a, cudaEventDisableTiming);
        cudaEventCreateWithFlags(&ev1b, cudaEventDisableTiming);
        cudaEventCreateWithFlags(&evR,  cudaEventDisableTiming);
        cudaEventCreateWithFlags(&ev2,  cudaEventDisableTiming);
        cudaEventCreateWithFlags(&evT1, cudaEventDisableTiming);
        cudaEventCreateWithFlags(&evT2, cudaEventDisableTiming);
        ready = 1;
    }

    __half* w1h; cudaGetSymbolAddress((void**)&w1h, g_W1h);
    __half* w2h; cudaGetSymbolAddress((void**)&w2h, g_W2h);

    const int WBLK  = NT*DC*DH/8192;       // 4096 blocks per weight tensor
    const int HALF  = WBLK/2;
    const size_t HOFF = (size_t)HALF * 8192;

    zero_counts_kernel<<<1, 32>>>();
    cudaEventRecord(ev0, 0);
    cudaStreamWaitEvent(s1, ev0, 0);
    cudaStreamWaitEvent(s2, ev0, 0);

    // W1 converts split across side streams (ready earliest).
    convert_f2h_kernel<<<HALF, 256, 0, s1>>>(W1,        w1h);
    cudaEventRecord(ev1a, s1);
    convert_f2h_kernel<<<HALF, 256, 0, s2>>>(W1 + HOFF, w1h + HOFF);
    cudaEventRecord(ev1b, s2);

    // Routing on the origin stream (concurrent with W1 converts).
    routing_kernel<<<NTOK/8, 256>>>(x, pe, pwp, cwp, pos_sigs, content_sigs);
    finalize_kernel<<<1, 1>>>();
    cudaEventRecord(evR, 0);

    // W2 converts on the origin stream: overlap with gemm1 groups below.
    convert_f2h_kernel<<<HALF, 256>>>(W2,        w2h);
    convert_f2h_kernel<<<HALF, 256>>>(W2 + HOFF, w2h + HOFF);
    cudaEventRecord(ev2, 0);

    // Group pipelines: gemm1(g) -> gemm2(g), groups overlap across streams.
    cudaStreamWaitEvent(s1, evR,  0);
    cudaStreamWaitEvent(s1, ev1b, 0);      // needs both W1 halves
    gemm1_kernel<<<dim3(MAXG, DH/BN), 128, SMEM_DYN, s1>>>(0, b1);
    cudaStreamWaitEvent(s1, ev2, 0);
    gemm2_kernel<<<dim3(MAXG, DC/BN), 128, SMEM_DYN, s1>>>(0, b2, out);
    cudaEventRecord(evT1, s1);

    cudaStreamWaitEvent(s2, evR,  0);
    cudaStreamWaitEvent(s2, ev1a, 0);
    gemm1_kernel<<<dim3(MAXG, DH/BN), 128, SMEM_DYN, s2>>>(1, b1);
    cudaStreamWaitEvent(s2, ev2, 0);
    gemm2_kernel<<<dim3(MAXG, DC/BN), 128, SMEM_DYN, s2>>>(1, b2, out);
    cudaEventRecord(evT2, s2);

    // Join side streams back into the capture-origin stream.
    cudaStreamWaitEvent(0, evT1, 0);
    cudaStreamWaitEvent(0, evT2, 0);
}